// round 6
// baseline (speedup 1.0000x reference)
#include <cuda_runtime.h>
#include <math.h>

#define NB     2048
#define KOBJ   8
#define H1     250
#define ROWS   (NB*KOBJ)       // 16384

__device__ float g_s1 [ROWS*H1];
__device__ float g_P  [ROWS*H1];
__device__ float g_Q  [ROWS*H1];
__device__ float g_eff[ROWS*H1];

typedef unsigned long long u64;

__device__ __forceinline__ float warp_sum(float v) {
#pragma unroll
    for (int o = 16; o; o >>= 1) v += __shfl_xor_sync(0xffffffffu, v, o);
    return v;
}
__device__ __forceinline__ void ffma2(u64& d, u64 a, u64 b) {
    asm("fma.rn.f32x2 %0, %1, %2, %0;" : "+l"(d) : "l"(a), "l"(b));
}
__device__ __forceinline__ float2 unpk(u64 v) {
    float2 f;
    asm("mov.b64 {%0, %1}, %2;" : "=f"(f.x), "=f"(f.y) : "l"(v));
    return f;
}
__device__ __forceinline__ void cp8(void* s, const void* g) {
    asm volatile("cp.async.ca.shared.global [%0], [%1], 8;"
                 :: "r"((unsigned)__cvta_generic_to_shared(s)), "l"(g));
}
__device__ __forceinline__ void cp4(void* s, const void* g) {
    asm volatile("cp.async.ca.shared.global [%0], [%1], 4;"
                 :: "r"((unsigned)__cvta_generic_to_shared(s)), "l"(g));
}
#define CP_COMMIT() asm volatile("cp.async.commit_group;")
#define CP_WAIT1()  asm volatile("cp.async.wait_group 1;")

__device__ __forceinline__ int colmap(int tx, int cc) {
    return (cc < 4) ? (tx * 4 + cc) : (128 + tx * 4 + (cc - 4));
}

// ---------------------------------------------------------------------------
// Tiled SGEMM: BM=64, BN=256(>=N), BK=16; 256 threads; dynamic smem.
// A-tile stored PRE-DUPLICATED ({a,a} pairs) -> inner loop has no dup movs.
// W double-buffered via cp.async; A staged through registers (LDG early,
// STS after compute). EPI==0 plain, EPI==1 +bias/relu/LN.
// smem: sA[2][64*40] (dup'd) | sW[2][16*256]  = 13312 floats = 53248 B
// ---------------------------------------------------------------------------
template <int EPI>
__global__ __launch_bounds__(256, 2)
void gemm_kernel(const float* __restrict__ A, const float* __restrict__ W,
                 const float* __restrict__ bias, const float* __restrict__ g,
                 const float* __restrict__ bt, float* __restrict__ C,
                 int M, int K, int N)
{
    extern __shared__ float dsm[];
    float* sAb[2] = { dsm, dsm + 2560 };
    float* sWb[2] = { dsm + 5120, dsm + 9216 };
    const int tid = threadIdx.x;
    const int tx = tid & 31, ty = tid >> 5;
    const int row0 = blockIdx.x * 64;
    const int NT = (K + 15) >> 4;

    auto ldA = [&](int t, float2* f) {
        int kt = t * 16;
#pragma unroll
        for (int c = 0; c < 2; ++c) {
            int q = tid + c * 256;
            int r = q >> 3, c2 = (q & 7) * 2;
            int k = kt + c2;
            const float* src = &A[(size_t)(row0 + r) * K + k];
            float2 v;
            if (k + 1 < K) v = *(const float2*)src;
            else { v.x = (k < K) ? src[0] : 0.f; v.y = 0.f; }
            f[c] = v;
        }
    };
    auto stA = [&](int buf, const float2* f) {
#pragma unroll
        for (int c = 0; c < 2; ++c) {
            int q = tid + c * 256;
            int r = q >> 3, c2 = (q & 7) * 2;
            float2* d = (float2*)&sAb[buf][r * 40 + 2 * c2];
            d[0] = make_float2(f[c].x, f[c].x);
            d[1] = make_float2(f[c].y, f[c].y);
        }
    };
    auto issueW = [&](int t, int buf) {
        int kt = t * 16;
#pragma unroll
        for (int c = 0; c < 8; ++c) {
            int q = tid + c * 256;
            int kk = q >> 7, n0 = (q & 127) * 2;
            int k = kt + kk;
            float* d = &sWb[buf][kk * 256 + n0];
            if (k < K && n0 + 2 <= N)   cp8(d, &W[(size_t)k * N + n0]);
            else if (k < K && n0 < N) { cp4(d, &W[(size_t)k * N + n0]); d[1] = 0.f; }
            else *(float2*)d = make_float2(0.f, 0.f);
        }
    };

    u64 acc2[8][4];
#pragma unroll
    for (int r = 0; r < 8; ++r)
#pragma unroll
        for (int p = 0; p < 4; ++p) acc2[r][p] = 0ull;

    { float2 f0[2]; ldA(0, f0); stA(0, f0); }
    issueW(0, 0); CP_COMMIT();

    for (int t = 0; t < NT; ++t) {
        float2 fn[2];
        if (t + 1 < NT) { ldA(t + 1, fn); issueW(t + 1, (t + 1) & 1); }
        CP_COMMIT();
        CP_WAIT1();
        __syncthreads();
        const float* aT = sAb[t & 1];
        const float* wT = sWb[t & 1];
#pragma unroll
        for (int kk = 0; kk < 16; ++kk) {
            ulonglong2 wv0 = *(const ulonglong2*)&wT[kk * 256 + tx * 4];
            ulonglong2 wv1 = *(const ulonglong2*)&wT[kk * 256 + 128 + tx * 4];
            u64 w2[4] = {wv0.x, wv0.y, wv1.x, wv1.y};
#pragma unroll
            for (int rr = 0; rr < 8; ++rr) {
                u64 a = *(const u64*)&aT[(ty * 8 + rr) * 40 + 2 * kk];
#pragma unroll
                for (int p = 0; p < 4; ++p) ffma2(acc2[rr][p], a, w2[p]);
            }
        }
        if (t + 1 < NT) stA((t + 1) & 1, fn);
        __syncthreads();
    }

    if (EPI == 0) {
#pragma unroll
        for (int rr = 0; rr < 8; ++rr) {
            int row = row0 + ty * 8 + rr;
#pragma unroll
            for (int p = 0; p < 4; ++p) {
                float2 f = unpk(acc2[rr][p]);
                int n0 = colmap(tx, 2 * p);
                if (n0 < N)     C[(size_t)row * N + n0]     = f.x;
                if (n0 + 1 < N) C[(size_t)row * N + n0 + 1] = f.y;
            }
        }
    } else {
        float invN = 1.f / (float)N;
#pragma unroll
        for (int rr = 0; rr < 8; ++rr) {
            int row = row0 + ty * 8 + rr;
            float v[8]; float s = 0.f;
#pragma unroll
            for (int cc = 0; cc < 8; ++cc) {
                float2 f = unpk(acc2[rr][cc >> 1]);
                float raw = (cc & 1) ? f.y : f.x;
                int n = colmap(tx, cc);
                float t = 0.f;
                if (n < N) t = fmaxf(raw + bias[n], 0.f);
                v[cc] = t; s += t;
            }
            s = warp_sum(s);
            float mu = s * invN;
            float q = 0.f;
#pragma unroll
            for (int cc = 0; cc < 8; ++cc) {
                int n = colmap(tx, cc);
                if (n < N) { float d = v[cc] - mu; q += d * d; }
            }
            q = warp_sum(q);
            float rs = rsqrtf(q * invN + 1e-5f);
#pragma unroll
            for (int cc = 0; cc < 8; ++cc) {
                int n = colmap(tx, cc);
                if (n < N) C[(size_t)row * N + n] = (v[cc] - mu) * rs * g[n] + bt[n];
            }
        }
    }
}

// ---------------------------------------------------------------------------
// Output GEMM: [s1|effect|x] @ out_W + out_b. K=1076, N=250. Same scheme.
// ---------------------------------------------------------------------------
__global__ __launch_bounds__(256, 2)
void out_gemm_kernel(const float* __restrict__ s1, const float* __restrict__ eff,
                     const float* __restrict__ x, const float* __restrict__ W,
                     const float* __restrict__ bias, float* __restrict__ C)
{
    const int K = 1076, N = 250;
    extern __shared__ float dsm[];
    float* sAb[2] = { dsm, dsm + 2560 };
    float* sWb[2] = { dsm + 5120, dsm + 9216 };
    const int tid = threadIdx.x;
    const int tx = tid & 31, ty = tid >> 5;
    const int row0 = blockIdx.x * 64;
    const int NT = (K + 15) >> 4;   // 68

    auto ldA = [&](int t, float* f) {
        int kt = t * 16;
#pragma unroll
        for (int c = 0; c < 4; ++c) {
            int q = tid + c * 256;
            int r = q >> 4, kk = q & 15;
            int k = kt + kk;
            int row = row0 + r;
            float av = 0.f;
            if (k < 250)       av = s1 [(size_t)row * 250 + k];
            else if (k < 500)  av = eff[(size_t)row * 250 + (k - 250)];
            else if (k < 1076) av = x  [(size_t)row * 576 + (k - 500)];
            f[c] = av;
        }
    };
    auto stA = [&](int buf, const float* f) {
#pragma unroll
        for (int c = 0; c < 4; ++c) {
            int q = tid + c * 256;
            int r = q >> 4, kk = q & 15;
            *(float2*)&sAb[buf][r * 40 + 2 * kk] = make_float2(f[c], f[c]);
        }
    };
    auto issueW = [&](int t, int buf) {
        int kt = t * 16;
#pragma unroll
        for (int c = 0; c < 8; ++c) {
            int q = tid + c * 256;
            int kk = q >> 7, n0 = (q & 127) * 2;
            int k = kt + kk;
            float* d = &sWb[buf][kk * 256 + n0];
            if (k < K && n0 + 2 <= N)   cp8(d, &W[(size_t)k * N + n0]);
            else if (k < K && n0 < N) { cp4(d, &W[(size_t)k * N + n0]); d[1] = 0.f; }
            else *(float2*)d = make_float2(0.f, 0.f);
        }
    };

    u64 acc2[8][4];
#pragma unroll
    for (int r = 0; r < 8; ++r)
#pragma unroll
        for (int p = 0; p < 4; ++p) acc2[r][p] = 0ull;

    { float f0[4]; ldA(0, f0); stA(0, f0); }
    issueW(0, 0); CP_COMMIT();

    for (int t = 0; t < NT; ++t) {
        float fn[4];
        if (t + 1 < NT) { ldA(t + 1, fn); issueW(t + 1, (t + 1) & 1); }
        CP_COMMIT();
        CP_WAIT1();
        __syncthreads();
        const float* aT = sAb[t & 1];
        const float* wT = sWb[t & 1];
#pragma unroll
        for (int kk = 0; kk < 16; ++kk) {
            ulonglong2 wv0 = *(const ulonglong2*)&wT[kk * 256 + tx * 4];
            ulonglong2 wv1 = *(const ulonglong2*)&wT[kk * 256 + 128 + tx * 4];
            u64 w2[4] = {wv0.x, wv0.y, wv1.x, wv1.y};
#pragma unroll
            for (int rr = 0; rr < 8; ++rr) {
                u64 a = *(const u64*)&aT[(ty * 8 + rr) * 40 + 2 * kk];
#pragma unroll
                for (int p = 0; p < 4; ++p) ffma2(acc2[rr][p], a, w2[p]);
            }
        }
        if (t + 1 < NT) stA((t + 1) & 1, fn);
        __syncthreads();
    }
#pragma unroll
    for (int rr = 0; rr < 8; ++rr) {
        int row = row0 + ty * 8 + rr;
#pragma unroll
        for (int p = 0; p < 4; ++p) {
            float2 f = unpk(acc2[rr][p]);
            int n0 = colmap(tx, 2 * p);
            if (n0 < N)     C[(size_t)row * N + n0]     = f.x + bias[n0];
            if (n0 + 1 < N) C[(size_t)row * N + n0 + 1] = f.y + bias[n0 + 1];
        }
    }
}

// ---------------------------------------------------------------------------
// Fused pair kernel v2: 512 threads, one block per b (56 rows).
// sC stored DUPLICATED (56 x 512 floats) -> FFMA2 feeds directly from LDS.
// att: warps 0..13 x 4 rows, 100 cols (4/lane).  ctx: warp-pairs, 7 rows x
// 128-col half each; LN row stats exchanged via sRed.
// smem: sC 28672 | union 8192 (staging / W tiles dbl-buf) | sAtt 64 | sRed 224
//   = 37152 floats = 148608 B  (1 block/SM)
// ---------------------------------------------------------------------------
#define P_SC    0
#define P_UN    28672
#define P_ATT   (P_UN + 8192)      /* 36864 */
#define P_RED   (P_ATT + 64)       /* 36928 */
#define P_TOT   (P_RED + 224)      /* 37152 floats */

__global__ __launch_bounds__(512, 1)
void pair_kernel(const float* __restrict__ P, const float* __restrict__ Q,
                 const float* __restrict__ core_b, const float* __restrict__ core_g,
                 const float* __restrict__ core_bt,
                 const float* __restrict__ ctxW, const float* __restrict__ ctx_b,
                 const float* __restrict__ ctx_g, const float* __restrict__ ctx_bt,
                 const float* __restrict__ attW1, const float* __restrict__ att_b1,
                 const float* __restrict__ att_g, const float* __restrict__ att_bt,
                 const float* __restrict__ attW2, const float* __restrict__ att_b2,
                 float* __restrict__ effect)
{
    extern __shared__ float sm[];
    float* sC   = sm + P_SC;    // dup'd core_out, row stride 512
    float* sUN  = sm + P_UN;    // staging / W tiles
    float* sAtt = sm + P_ATT;
    float* sRed = sm + P_RED;
    float* sP   = sUN;
    float* sQ   = sUN + 2016;

    const int tid = threadIdx.x;
    const int tx = tid & 31, wy = tid >> 5;   // 16 warps
    const int b = blockIdx.x;

    // --- phase 1: stage P,Q; build dup'd core_out ---
    for (int idx = tid; idx < 8 * 250; idx += 512) {
        int i = idx / 250, c = idx % 250;
        sP[i * 252 + c] = P[(size_t)(b * 8 + i) * 250 + c];
        sQ[i * 252 + c] = Q[(size_t)(b * 8 + i) * 250 + c];
    }
    __syncthreads();

    for (int r = wy; r < 56; r += 16) {
        int i = r / 7, jj = r % 7;
        int j = jj + (jj >= i ? 1 : 0);
        float v[8]; float s = 0.f;
#pragma unroll
        for (int t = 0; t < 8; ++t) {
            int c = tx + 32 * t;
            float val = 0.f;
            if (c < 250) val = fmaxf(sP[i * 252 + c] + sQ[j * 252 + c] + core_b[c], 0.f);
            v[t] = val; s += val;
        }
        s = warp_sum(s);
        float mu = s * (1.f / 250.f);
        float q = 0.f;
#pragma unroll
        for (int t = 0; t < 8; ++t) {
            int c = tx + 32 * t;
            if (c < 250) { float d = v[t] - mu; q += d * d; }
        }
        q = warp_sum(q);
        float rs = rsqrtf(q * (1.f / 250.f) + 1e-5f);
#pragma unroll
        for (int t = 0; t < 8; ++t) {
            int c = tx + 32 * t;
            float o = (c < 250) ? (v[t] - mu) * rs * core_g[c] + core_bt[c] : 0.f;
            *(float2*)&sC[r * 512 + 2 * c] = make_float2(o, o);
        }
    }
    __syncthreads();   // staging dead; W tiles may overwrite sUN

    // --- phase 2: att GEMM (warps 0..13, rows wy*4..wy*4+3, 100 cols) ---
    auto issue_att = [&](int t, int buf) {
        int kt = t * 16;
#pragma unroll
        for (int c = 0; c < 2; ++c) {
            int q = tid + c * 512;
            int kk = q >> 6, n0 = (q & 63) * 2;
            int k = kt + kk;
            float* d = &sUN[buf * 2048 + kk * 128 + n0];
            if (k < 250 && n0 + 2 <= 100) cp8(d, &attW1[(size_t)k * 100 + n0]);
            else *(float2*)d = make_float2(0.f, 0.f);
        }
    };
    auto issue_ctx = [&](int t, int buf) {
        int kt = t * 16;
#pragma unroll
        for (int c = 0; c < 4; ++c) {
            int q = tid + c * 512;
            int kk = q >> 7, n0 = (q & 127) * 2;
            int k = kt + kk;
            float* d = &sUN[buf * 4096 + kk * 256 + n0];
            if (k < 250 && n0 < 250) cp8(d, &ctxW[(size_t)k * 250 + n0]);
            else *(float2*)d = make_float2(0.f, 0.f);
        }
    };

    u64 accA[4][2];
#pragma unroll
    for (int r = 0; r < 4; ++r) { accA[r][0] = 0ull; accA[r][1] = 0ull; }

    issue_att(0, 0); CP_COMMIT();
    for (int t = 0; t < 16; ++t) {
        if (t < 15) issue_att(t + 1, (t + 1) & 1);
        CP_COMMIT();
        CP_WAIT1();
        __syncthreads();
        if (wy < 14) {
            const float* wT = sUN + (t & 1) * 2048;
            int kt = t * 16;
#pragma unroll
            for (int kk = 0; kk < 16; ++kk) {
                ulonglong2 wv = *(const ulonglong2*)&wT[kk * 128 + tx * 4];
                u64 w2[2] = {wv.x, wv.y};
#pragma unroll
                for (int rr = 0; rr < 4; ++rr) {
                    u64 a = *(const u64*)&sC[(wy * 4 + rr) * 512 + 2 * (kt + kk)];
                    ffma2(accA[rr][0], a, w2[0]);
                    ffma2(accA[rr][1], a, w2[1]);
                }
            }
        }
        __syncthreads();
    }

    // prefetch ctx tile 0 before epilogue math
    issue_ctx(0, 0); CP_COMMIT();

    if (wy < 14) {
#pragma unroll
        for (int rr = 0; rr < 4; ++rr) {
            int row = wy * 4 + rr;
            float h[4]; float s = 0.f;
#pragma unroll
            for (int cc = 0; cc < 4; ++cc) {
                float2 f = unpk(accA[rr][cc >> 1]);
                float raw = (cc & 1) ? f.y : f.x;
                int c = tx * 4 + cc;
                float t = 0.f;
                if (c < 100) t = tanhf(raw + att_b1[c]);
                h[cc] = t; s += t;
            }
            s = warp_sum(s);
            float mu = s * (1.f / 100.f);
            float q = 0.f;
#pragma unroll
            for (int cc = 0; cc < 4; ++cc) {
                int c = tx * 4 + cc;
                if (c < 100) { float d = h[cc] - mu; q += d * d; }
            }
            q = warp_sum(q);
            float rs = rsqrtf(q * (1.f / 100.f) + 1e-5f);
            float p = 0.f;
#pragma unroll
            for (int cc = 0; cc < 4; ++cc) {
                int c = tx * 4 + cc;
                if (c < 100) p += ((h[cc] - mu) * rs * att_g[c] + att_bt[c]) * attW2[c];
            }
            p = warp_sum(p);
            if (tx == 0) sAtt[row] = 1.f / (1.f + expf(-(p + att_b2[0])));
        }
    }
    __syncthreads();

    // --- phase 3: ctx GEMM (warp-pairs: ig = wy>>1, col half = wy&1) ---
    const int ig = wy >> 1, half = wy & 1;
    const int cbase = half * 128;

    u64 accC[7][2];
#pragma unroll
    for (int r = 0; r < 7; ++r) { accC[r][0] = 0ull; accC[r][1] = 0ull; }

    for (int t = 0; t < 16; ++t) {
        if (t < 15) issue_ctx(t + 1, (t + 1) & 1);
        CP_COMMIT();
        CP_WAIT1();
        __syncthreads();
        const float* wT = sUN + (t & 1) * 4096;
        int kt = t * 16;
#pragma unroll
        for (int kk = 0; kk < 16; ++kk) {
            ulonglong2 wv = *(const ulonglong2*)&wT[kk * 256 + cbase + tx * 4];
            u64 w2[2] = {wv.x, wv.y};
#pragma unroll
            for (int rr = 0; rr < 7; ++rr) {
                u64 a = *(const u64*)&sC[(ig * 7 + rr) * 512 + 2 * (kt + kk)];
                ffma2(accC[rr][0], a, w2[0]);
                ffma2(accC[rr][1], a, w2[1]);
            }
        }
        __syncthreads();
    }

    // ctx epilogue: partial row stats -> exchange -> LN + effect reduce
    float v[7][4];
#pragma unroll
    for (int rr = 0; rr < 7; ++rr) {
        int row = ig * 7 + rr;
        float s = 0.f, sq = 0.f;
#pragma unroll
        for (int cc = 0; cc < 4; ++cc) {
            int c = cbase + tx * 4 + cc;
            float2 f = unpk(accC[rr][cc >> 1]);
            float raw = (cc & 1) ? f.y : f.x;
            float t = 0.f;
            if (c < 250) t = fmaxf(raw + ctx_b[c], 0.f);
            v[rr][cc] = t; s += t; sq += t * t;
        }
        s = warp_sum(s); sq = warp_sum(sq);
        if (tx == 0) { sRed[row * 4 + half * 2] = s; sRed[row * 4 + half * 2 + 1] = sq; }
    }
    __syncthreads();

    float eff[4] = {0.f, 0.f, 0.f, 0.f};
#pragma unroll
    for (int rr = 0; rr < 7; ++rr) {
        int row = ig * 7 + rr;
        float sum = sRed[row * 4 + 0] + sRed[row * 4 + 2];
        float sqs = sRed[row * 4 + 1] + sRed[row * 4 + 3];
        float mu = sum * (1.f / 250.f);
        float var = fmaxf(sqs * (1.f / 250.f) - mu * mu, 0.f);
        float rs = rsqrtf(var + 1e-5f);
        float aw = sAtt[row];
#pragma unroll
        for (int cc = 0; cc < 4; ++cc) {
            int c = cbase + tx * 4 + cc;
            if (c < 250) eff[cc] += ((v[rr][cc] - mu) * rs * ctx_g[c] + ctx_bt[c]) * aw;
        }
    }
#pragma unroll
    for (int cc = 0; cc < 4; ++cc) {
        int c = cbase + tx * 4 + cc;
        if (c < 250) effect[(size_t)(b * 8 + ig) * 250 + c] = eff[cc];
    }
}

// ---------------------------------------------------------------------------
extern "C" void kernel_launch(void* const* d_in, const int* in_sizes, int n_in,
                              void* d_out, int out_size)
{
    const float* x      = (const float*)d_in[0];
    const float* state  = (const float*)d_in[1];
    const float* enc_W  = (const float*)d_in[2];
    const float* enc_b  = (const float*)d_in[3];
    const float* enc_g  = (const float*)d_in[4];
    const float* enc_bt = (const float*)d_in[5];
    const float* core_W = (const float*)d_in[6];
    const float* core_b = (const float*)d_in[7];
    const float* core_g = (const float*)d_in[8];
    const float* core_bt= (const float*)d_in[9];
    const float* ctx_W  = (const float*)d_in[10];
    const float* ctx_b  = (const float*)d_in[11];
    const float* ctx_g  = (const float*)d_in[12];
    const float* ctx_bt = (const float*)d_in[13];
    const float* att_W1 = (const float*)d_in[14];
    const float* att_b1 = (const float*)d_in[15];
    const float* att_g  = (const float*)d_in[16];
    const float* att_bt = (const float*)d_in[17];
    const float* att_W2 = (const float*)d_in[18];
    const float* att_b2 = (const float*)d_in[19];
    const float* out_W  = (const float*)d_in[20];
    const float* out_b  = (const float*)d_in[21];
    float* out = (float*)d_out;

    float *p_s1, *p_P, *p_Q, *p_eff;
    cudaGetSymbolAddress((void**)&p_s1,  g_s1);
    cudaGetSymbolAddress((void**)&p_P,   g_P);
    cudaGetSymbolAddress((void**)&p_Q,   g_Q);
    cudaGetSymbolAddress((void**)&p_eff, g_eff);

    const int GEMM_SMEM = 13312 * (int)sizeof(float);   // 53248 B
    const int PAIR_SMEM = P_TOT * (int)sizeof(float);   // 148608 B
    cudaFuncSetAttribute(gemm_kernel<0>, cudaFuncAttributeMaxDynamicSharedMemorySize, GEMM_SMEM);
    cudaFuncSetAttribute(gemm_kernel<1>, cudaFuncAttributeMaxDynamicSharedMemorySize, GEMM_SMEM);
    cudaFuncSetAttribute(out_gemm_kernel, cudaFuncAttributeMaxDynamicSharedMemorySize, GEMM_SMEM);
    cudaFuncSetAttribute(pair_kernel, cudaFuncAttributeMaxDynamicSharedMemorySize, PAIR_SMEM);

    gemm_kernel<1><<<ROWS / 64, 256, GEMM_SMEM>>>(state, enc_W, enc_b, enc_g, enc_bt,
                                                  p_s1, ROWS, 250, 250);
    gemm_kernel<0><<<ROWS / 64, 256, GEMM_SMEM>>>(p_s1, core_W, nullptr, nullptr, nullptr,
                                                  p_P, ROWS, 250, 250);
    gemm_kernel<0><<<ROWS / 64, 256, GEMM_SMEM>>>(p_s1, core_W + 250 * 250, nullptr, nullptr, nullptr,
                                                  p_Q, ROWS, 250, 250);
    pair_kernel<<<NB, 512, PAIR_SMEM>>>(
        p_P, p_Q, core_b, core_g, core_bt,
        ctx_W, ctx_b, ctx_g, ctx_bt,
        att_W1, att_b1, att_g, att_bt,
        att_W2, att_b2, p_eff);
    out_gemm_kernel<<<ROWS / 64, 256, GEMM_SMEM>>>(p_s1, p_eff, x, out_W, out_b, out);
}

// round 7
// speedup vs baseline: 1.4094x; 1.4094x over previous
#include <cuda_runtime.h>
#include <math.h>

#define NB     2048
#define KOBJ   8
#define H1     250
#define ROWS   (NB*KOBJ)       // 16384

__device__ float g_s1 [ROWS*H1];
__device__ float g_P  [ROWS*H1];
__device__ float g_Q  [ROWS*H1];
__device__ float g_eff[ROWS*H1];

typedef unsigned long long u64;

__device__ __forceinline__ float warp_sum(float v) {
#pragma unroll
    for (int o = 16; o; o >>= 1) v += __shfl_xor_sync(0xffffffffu, v, o);
    return v;
}
__device__ __forceinline__ void ffma2(u64& d, u64 a, u64 b) {
    asm("fma.rn.f32x2 %0, %1, %2, %0;" : "+l"(d) : "l"(a), "l"(b));
}
__device__ __forceinline__ u64 dup2(float x) {
    u64 r;
    asm("mov.b64 %0, {%1, %1};" : "=l"(r) : "r"(__float_as_uint(x)));
    return r;
}
__device__ __forceinline__ float2 unpk(u64 v) {
    float2 f;
    asm("mov.b64 {%0, %1}, %2;" : "=f"(f.x), "=f"(f.y) : "l"(v));
    return f;
}
__device__ __forceinline__ float fsel(float4 v, int m) {
    return (m == 0) ? v.x : (m == 1) ? v.y : (m == 2) ? v.z : v.w;
}
__device__ __forceinline__ void cp8(void* s, const void* g) {
    asm volatile("cp.async.ca.shared.global [%0], [%1], 8;"
                 :: "r"((unsigned)__cvta_generic_to_shared(s)), "l"(g));
}
__device__ __forceinline__ void cp4(void* s, const void* g) {
    asm volatile("cp.async.ca.shared.global [%0], [%1], 4;"
                 :: "r"((unsigned)__cvta_generic_to_shared(s)), "l"(g));
}
#define CP_COMMIT() asm volatile("cp.async.commit_group;")
#define CP_WAIT1()  asm volatile("cp.async.wait_group 1;")

__device__ __forceinline__ int colmap(int tx, int cc) {
    return (cc < 4) ? (tx * 4 + cc) : (128 + tx * 4 + (cc - 4));
}

// ---------------------------------------------------------------------------
// Tiled SGEMM (R5-best): BM=64, BN=256(>=N), BK=16; 256 threads;
// cp.async double-buffered A+W tiles; dup2 in loop; FFMA2 accumulators.
// ---------------------------------------------------------------------------
template <int EPI>
__global__ __launch_bounds__(256, 2)
void gemm_kernel(const float* __restrict__ A, const float* __restrict__ W,
                 const float* __restrict__ bias, const float* __restrict__ g,
                 const float* __restrict__ bt, float* __restrict__ C,
                 int M, int K, int N)
{
    __shared__ float sA[2][64 * 20];
    __shared__ float sW[2][16 * 256];
    const int tid = threadIdx.x;
    const int tx = tid & 31, ty = tid >> 5;
    const int row0 = blockIdx.x * 64;
    const int NT = (K + 15) >> 4;

    auto issue = [&](int t, int buf) {
        int kt = t * 16;
#pragma unroll
        for (int c = 0; c < 2; ++c) {
            int q = tid + c * 256;
            int r = q >> 3, kk0 = (q & 7) * 2;
            int k = kt + kk0;
            float* d = &sA[buf][r * 20 + kk0];
            if (k + 2 <= K)     cp8(d, &A[(size_t)(row0 + r) * K + k]);
            else if (k < K) { cp4(d, &A[(size_t)(row0 + r) * K + k]); d[1] = 0.f; }
            else *(float2*)d = make_float2(0.f, 0.f);
        }
#pragma unroll
        for (int c = 0; c < 8; ++c) {
            int q = tid + c * 256;
            int kk = q >> 7, n0 = (q & 127) * 2;
            int k = kt + kk;
            float* d = &sW[buf][kk * 256 + n0];
            if (k < K && n0 + 2 <= N)   cp8(d, &W[(size_t)k * N + n0]);
            else if (k < K && n0 < N) { cp4(d, &W[(size_t)k * N + n0]); d[1] = 0.f; }
            else *(float2*)d = make_float2(0.f, 0.f);
        }
    };

    u64 acc2[8][4];
#pragma unroll
    for (int r = 0; r < 8; ++r)
#pragma unroll
        for (int p = 0; p < 4; ++p) acc2[r][p] = 0ull;

    issue(0, 0); CP_COMMIT();
    for (int t = 0; t < NT; ++t) {
        if (t + 1 < NT) issue(t + 1, (t + 1) & 1);
        CP_COMMIT();
        CP_WAIT1();
        __syncthreads();
        const float* aT = sA[t & 1];
        const float* wT = sW[t & 1];
#pragma unroll
        for (int k4 = 0; k4 < 4; ++k4) {
            float4 a4[8];
#pragma unroll
            for (int rr = 0; rr < 8; ++rr)
                a4[rr] = *(const float4*)&aT[(ty * 8 + rr) * 20 + k4 * 4];
#pragma unroll
            for (int m = 0; m < 4; ++m) {
                int kk = k4 * 4 + m;
                ulonglong2 wv0 = *(const ulonglong2*)&wT[kk * 256 + tx * 4];
                ulonglong2 wv1 = *(const ulonglong2*)&wT[kk * 256 + 128 + tx * 4];
                u64 w2[4] = {wv0.x, wv0.y, wv1.x, wv1.y};
#pragma unroll
                for (int rr = 0; rr < 8; ++rr) {
                    u64 ad = dup2(fsel(a4[rr], m));
#pragma unroll
                    for (int p = 0; p < 4; ++p) ffma2(acc2[rr][p], ad, w2[p]);
                }
            }
        }
        __syncthreads();
    }

    if (EPI == 0) {
#pragma unroll
        for (int rr = 0; rr < 8; ++rr) {
            int row = row0 + ty * 8 + rr;
#pragma unroll
            for (int p = 0; p < 4; ++p) {
                float2 f = unpk(acc2[rr][p]);
                int n0 = colmap(tx, 2 * p);
                if (n0 < N)     C[(size_t)row * N + n0]     = f.x;
                if (n0 + 1 < N) C[(size_t)row * N + n0 + 1] = f.y;
            }
        }
    } else {
        float invN = 1.f / (float)N;
#pragma unroll
        for (int rr = 0; rr < 8; ++rr) {
            int row = row0 + ty * 8 + rr;
            float v[8]; float s = 0.f;
#pragma unroll
            for (int cc = 0; cc < 8; ++cc) {
                float2 f = unpk(acc2[rr][cc >> 1]);
                float raw = (cc & 1) ? f.y : f.x;
                int n = colmap(tx, cc);
                float t = 0.f;
                if (n < N) t = fmaxf(raw + bias[n], 0.f);
                v[cc] = t; s += t;
            }
            s = warp_sum(s);
            float mu = s * invN;
            float q = 0.f;
#pragma unroll
            for (int cc = 0; cc < 8; ++cc) {
                int n = colmap(tx, cc);
                if (n < N) { float d = v[cc] - mu; q += d * d; }
            }
            q = warp_sum(q);
            float rs = rsqrtf(q * invN + 1e-5f);
#pragma unroll
            for (int cc = 0; cc < 8; ++cc) {
                int n = colmap(tx, cc);
                if (n < N) C[(size_t)row * N + n] = (v[cc] - mu) * rs * g[n] + bt[n];
            }
        }
    }
}

// ---------------------------------------------------------------------------
// Output GEMM (R5-best): [s1|effect|x] @ out_W + out_b. K=1076, N=250.
// ---------------------------------------------------------------------------
__global__ __launch_bounds__(256, 2)
void out_gemm_kernel(const float* __restrict__ s1, const float* __restrict__ eff,
                     const float* __restrict__ x, const float* __restrict__ W,
                     const float* __restrict__ bias, float* __restrict__ C)
{
    const int K = 1076, N = 250;
    __shared__ float sA[2][64 * 20];
    __shared__ float sW[2][16 * 256];
    const int tid = threadIdx.x;
    const int tx = tid & 31, ty = tid >> 5;
    const int row0 = blockIdx.x * 64;
    const int NT = (K + 15) >> 4;   // 68

    auto issue = [&](int t, int buf) {
        int kt = t * 16;
#pragma unroll
        for (int c = 0; c < 4; ++c) {
            int q = tid + c * 256;
            int r = q >> 4, kk = q & 15;
            int k = kt + kk;
            int row = row0 + r;
            float* d = &sA[buf][r * 20 + kk];
            if (k < 250)       cp4(d, &s1 [(size_t)row * 250 + k]);
            else if (k < 500)  cp4(d, &eff[(size_t)row * 250 + (k - 250)]);
            else if (k < 1076) cp4(d, &x  [(size_t)row * 576 + (k - 500)]);
            else *d = 0.f;
        }
#pragma unroll
        for (int c = 0; c < 8; ++c) {
            int q = tid + c * 256;
            int kk = q >> 7, n0 = (q & 127) * 2;
            int k = kt + kk;
            float* d = &sW[buf][kk * 256 + n0];
            if (k < K && n0 + 2 <= N)   cp8(d, &W[(size_t)k * N + n0]);
            else if (k < K && n0 < N) { cp4(d, &W[(size_t)k * N + n0]); d[1] = 0.f; }
            else *(float2*)d = make_float2(0.f, 0.f);
        }
    };

    u64 acc2[8][4];
#pragma unroll
    for (int r = 0; r < 8; ++r)
#pragma unroll
        for (int p = 0; p < 4; ++p) acc2[r][p] = 0ull;

    issue(0, 0); CP_COMMIT();
    for (int t = 0; t < NT; ++t) {
        if (t + 1 < NT) issue(t + 1, (t + 1) & 1);
        CP_COMMIT();
        CP_WAIT1();
        __syncthreads();
        const float* aT = sA[t & 1];
        const float* wT = sW[t & 1];
#pragma unroll
        for (int k4 = 0; k4 < 4; ++k4) {
            float4 a4[8];
#pragma unroll
            for (int rr = 0; rr < 8; ++rr)
                a4[rr] = *(const float4*)&aT[(ty * 8 + rr) * 20 + k4 * 4];
#pragma unroll
            for (int m = 0; m < 4; ++m) {
                int kk = k4 * 4 + m;
                ulonglong2 wv0 = *(const ulonglong2*)&wT[kk * 256 + tx * 4];
                ulonglong2 wv1 = *(const ulonglong2*)&wT[kk * 256 + 128 + tx * 4];
                u64 w2[4] = {wv0.x, wv0.y, wv1.x, wv1.y};
#pragma unroll
                for (int rr = 0; rr < 8; ++rr) {
                    u64 ad = dup2(fsel(a4[rr], m));
#pragma unroll
                    for (int p = 0; p < 4; ++p) ffma2(acc2[rr][p], ad, w2[p]);
                }
            }
        }
        __syncthreads();
    }
#pragma unroll
    for (int rr = 0; rr < 8; ++rr) {
        int row = row0 + ty * 8 + rr;
#pragma unroll
        for (int p = 0; p < 4; ++p) {
            float2 f = unpk(acc2[rr][p]);
            int n0 = colmap(tx, 2 * p);
            if (n0 < N)     C[(size_t)row * N + n0]     = f.x + bias[n0];
            if (n0 + 1 < N) C[(size_t)row * N + n0 + 1] = f.y + bias[n0 + 1];
        }
    }
}

// ---------------------------------------------------------------------------
// Fused pair kernel (R4 structure, BK=32): one block per b (56 rows).
// Plain LDG->STS tile loads, dup2 in loop, FFMA2. 8 load/compute phases
// per GEMM instead of 16 (halved barrier + exposed-load overhead).
// SMEM: sC 56x256 | union { sP/sQ staging(4032) , W tile 32x256(8192) } | sAtt
// ---------------------------------------------------------------------------
#define SC_STRIDE 256
#define SM_SC   0
#define SM_UN   (56 * SC_STRIDE)        /* 14336; union region 8192 floats */
#define SM_ATT  (SM_UN + 8192)          /* 22528 */
#define SM_TOT  (SM_ATT + 64)           /* 22592 floats = 90368 B */

__global__ __launch_bounds__(256, 2)
void pair_kernel(const float* __restrict__ P, const float* __restrict__ Q,
                 const float* __restrict__ core_b, const float* __restrict__ core_g,
                 const float* __restrict__ core_bt,
                 const float* __restrict__ ctxW, const float* __restrict__ ctx_b,
                 const float* __restrict__ ctx_g, const float* __restrict__ ctx_bt,
                 const float* __restrict__ attW1, const float* __restrict__ att_b1,
                 const float* __restrict__ att_g, const float* __restrict__ att_bt,
                 const float* __restrict__ attW2, const float* __restrict__ att_b2,
                 float* __restrict__ effect)
{
    extern __shared__ float sm[];
    float* sC   = sm + SM_SC;
    float* sP   = sm + SM_UN;            // staging (phase 1 only)
    float* sQ   = sm + SM_UN + 2016;
    float* sW   = sm + SM_UN;            // weight tiles (phases 2-3)
    float* sAtt = sm + SM_ATT;

    const int tid = threadIdx.x;
    const int tx = tid & 31, ty = tid >> 5;
    const int b = blockIdx.x;

    // --- phase 1: load P,Q rows, build core_out into sC ---
    for (int idx = tid; idx < 8 * 250; idx += 256) {
        int i = idx / 250, c = idx % 250;
        sP[i * 252 + c] = P[(size_t)(b * 8 + i) * 250 + c];
        sQ[i * 252 + c] = Q[(size_t)(b * 8 + i) * 250 + c];
    }
    __syncthreads();

    for (int r = ty; r < 56; r += 8) {
        int i = r / 7, jj = r % 7;
        int j = jj + (jj >= i ? 1 : 0);
        float v[8]; float s = 0.f;
#pragma unroll
        for (int t = 0; t < 8; ++t) {
            int c = tx + 32 * t;
            float val = 0.f;
            if (c < 250) val = fmaxf(sP[i * 252 + c] + sQ[j * 252 + c] + core_b[c], 0.f);
            v[t] = val; s += val;
        }
        s = warp_sum(s);
        float mu = s * (1.f / 250.f);
        float q = 0.f;
#pragma unroll
        for (int t = 0; t < 8; ++t) {
            int c = tx + 32 * t;
            if (c < 250) { float d = v[t] - mu; q += d * d; }
        }
        q = warp_sum(q);
        float rs = rsqrtf(q * (1.f / 250.f) + 1e-5f);
#pragma unroll
        for (int t = 0; t < 8; ++t) {
            int c = tx + 32 * t;
            if (c < 250) sC[r * SC_STRIDE + c] = (v[t] - mu) * rs * core_g[c] + core_bt[c];
            else         sC[r * SC_STRIDE + c] = 0.f;
        }
    }
    __syncthreads();   // staging dead; W tiles may overwrite

    // --- phase 2: attention GEMM 56 x 100, K=250, BK=32 (8 phases) ---
    u64 accA2[7][2];
#pragma unroll
    for (int r = 0; r < 7; ++r)
#pragma unroll
        for (int p = 0; p < 2; ++p) accA2[r][p] = 0ull;

    for (int t8 = 0; t8 < 8; ++t8) {
        int kt0 = t8 * 32;
        // load 32x128 att tile (zero-padded)
#pragma unroll
        for (int c = 0; c < 16; ++c) {
            int q = tid + c * 256;
            int kk = q >> 7, n = q & 127;
            int k = kt0 + kk;
            sW[kk * 128 + n] = (k < 250 && n < 100) ? attW1[(size_t)k * 100 + n] : 0.f;
        }
        __syncthreads();
#pragma unroll
        for (int k4 = 0; k4 < 8; ++k4) {
            int kt = kt0 + k4 * 4;
            float4 a4[7];
#pragma unroll
            for (int rr = 0; rr < 7; ++rr)
                a4[rr] = *(const float4*)&sC[(ty * 7 + rr) * SC_STRIDE + kt];
#pragma unroll
            for (int m = 0; m < 4; ++m) {
                int kk = k4 * 4 + m;
                ulonglong2 wv = *(const ulonglong2*)&sW[kk * 128 + tx * 4];
                u64 w2[2] = {wv.x, wv.y};
#pragma unroll
                for (int rr = 0; rr < 7; ++rr) {
                    u64 ad = dup2(fsel(a4[rr], m));
#pragma unroll
                    for (int p = 0; p < 2; ++p) ffma2(accA2[rr][p], ad, w2[p]);
                }
            }
        }
        __syncthreads();
    }

    // attention epilogue: tanh, LN(100), dot attW2, sigmoid
#pragma unroll
    for (int rr = 0; rr < 7; ++rr) {
        int row = ty * 7 + rr;
        float h[4]; float s = 0.f;
#pragma unroll
        for (int cc = 0; cc < 4; ++cc) {
            float2 f = unpk(accA2[rr][cc >> 1]);
            float raw = (cc & 1) ? f.y : f.x;
            int c = tx * 4 + cc;
            float t = 0.f;
            if (c < 100) t = tanhf(raw + att_b1[c]);
            h[cc] = t; s += t;
        }
        s = warp_sum(s);
        float mu = s * (1.f / 100.f);
        float q = 0.f;
#pragma unroll
        for (int cc = 0; cc < 4; ++cc) {
            int c = tx * 4 + cc;
            if (c < 100) { float d = h[cc] - mu; q += d * d; }
        }
        q = warp_sum(q);
        float rs = rsqrtf(q * (1.f / 100.f) + 1e-5f);
        float p = 0.f;
#pragma unroll
        for (int cc = 0; cc < 4; ++cc) {
            int c = tx * 4 + cc;
            if (c < 100) p += ((h[cc] - mu) * rs * att_g[c] + att_bt[c]) * attW2[c];
        }
        p = warp_sum(p);
        if (tx == 0) sAtt[row] = 1.f / (1.f + expf(-(p + att_b2[0])));
    }
    __syncthreads();

    // --- phase 3: ctx GEMM 56 x 250, K=250, BK=32 (8 phases) ---
    u64 accC2[7][4];
#pragma unroll
    for (int r = 0; r < 7; ++r)
#pragma unroll
        for (int p = 0; p < 4; ++p) accC2[r][p] = 0ull;

    for (int t8 = 0; t8 < 8; ++t8) {
        int kt0 = t8 * 32;
        // load 32x256 ctx tile (zero-padded)
#pragma unroll
        for (int c = 0; c < 32; ++c) {
            int k = kt0 + c;
            sW[c * 256 + tid] = (k < 250 && tid < 250) ? ctxW[(size_t)k * 250 + tid] : 0.f;
        }
        __syncthreads();
#pragma unroll
        for (int k4 = 0; k4 < 8; ++k4) {
            int kt = kt0 + k4 * 4;
            float4 a4[7];
#pragma unroll
            for (int rr = 0; rr < 7; ++rr)
                a4[rr] = *(const float4*)&sC[(ty * 7 + rr) * SC_STRIDE + kt];
#pragma unroll
            for (int m = 0; m < 4; ++m) {
                int kk = k4 * 4 + m;
                ulonglong2 wv0 = *(const ulonglong2*)&sW[kk * 256 + tx * 4];
                ulonglong2 wv1 = *(const ulonglong2*)&sW[kk * 256 + 128 + tx * 4];
                u64 w2[4] = {wv0.x, wv0.y, wv1.x, wv1.y};
#pragma unroll
                for (int rr = 0; rr < 7; ++rr) {
                    u64 ad = dup2(fsel(a4[rr], m));
#pragma unroll
                    for (int p = 0; p < 4; ++p) ffma2(accC2[rr][p], ad, w2[p]);
                }
            }
        }
        __syncthreads();
    }

    // --- ctx epilogue + effect reduce (warp ty owns i-group ty) ---
    float eff[8];
#pragma unroll
    for (int cc = 0; cc < 8; ++cc) eff[cc] = 0.f;
#pragma unroll
    for (int rr = 0; rr < 7; ++rr) {
        int row = ty * 7 + rr;
        float v[8]; float s = 0.f;
#pragma unroll
        for (int cc = 0; cc < 8; ++cc) {
            float2 f = unpk(accC2[rr][cc >> 1]);
            float raw = (cc & 1) ? f.y : f.x;
            int c = colmap(tx, cc);
            float t = 0.f;
            if (c < 250) t = fmaxf(raw + ctx_b[c], 0.f);
            v[cc] = t; s += t;
        }
        s = warp_sum(s);
        float mu = s * (1.f / 250.f);
        float q = 0.f;
#pragma unroll
        for (int cc = 0; cc < 8; ++cc) {
            int c = colmap(tx, cc);
            if (c < 250) { float d = v[cc] - mu; q += d * d; }
        }
        q = warp_sum(q);
        float rs = rsqrtf(q * (1.f / 250.f) + 1e-5f);
        float aw = sAtt[row];
#pragma unroll
        for (int cc = 0; cc < 8; ++cc) {
            int c = colmap(tx, cc);
            if (c < 250) eff[cc] += ((v[cc] - mu) * rs * ctx_g[c] + ctx_bt[c]) * aw;
        }
    }
#pragma unroll
    for (int cc = 0; cc < 8; ++cc) {
        int c = colmap(tx, cc);
        if (c < 250) effect[(size_t)(b * 8 + ty) * 250 + c] = eff[cc];
    }
}

// ---------------------------------------------------------------------------
extern "C" void kernel_launch(void* const* d_in, const int* in_sizes, int n_in,
                              void* d_out, int out_size)
{
    const float* x      = (const float*)d_in[0];
    const float* state  = (const float*)d_in[1];
    const float* enc_W  = (const float*)d_in[2];
    const float* enc_b  = (const float*)d_in[3];
    const float* enc_g  = (const float*)d_in[4];
    const float* enc_bt = (const float*)d_in[5];
    const float* core_W = (const float*)d_in[6];
    const float* core_b = (const float*)d_in[7];
    const float* core_g = (const float*)d_in[8];
    const float* core_bt= (const float*)d_in[9];
    const float* ctx_W  = (const float*)d_in[10];
    const float* ctx_b  = (const float*)d_in[11];
    const float* ctx_g  = (const float*)d_in[12];
    const float* ctx_bt = (const float*)d_in[13];
    const float* att_W1 = (const float*)d_in[14];
    const float* att_b1 = (const float*)d_in[15];
    const float* att_g  = (const float*)d_in[16];
    const float* att_bt = (const float*)d_in[17];
    const float* att_W2 = (const float*)d_in[18];
    const float* att_b2 = (const float*)d_in[19];
    const float* out_W  = (const float*)d_in[20];
    const float* out_b  = (const float*)d_in[21];
    float* out = (float*)d_out;

    float *p_s1, *p_P, *p_Q, *p_eff;
    cudaGetSymbolAddress((void**)&p_s1,  g_s1);
    cudaGetSymbolAddress((void**)&p_P,   g_P);
    cudaGetSymbolAddress((void**)&p_Q,   g_Q);
    cudaGetSymbolAddress((void**)&p_eff, g_eff);

    cudaFuncSetAttribute(pair_kernel, cudaFuncAttributeMaxDynamicSharedMemorySize,
                         SM_TOT * (int)sizeof(float));

    gemm_kernel<1><<<ROWS / 64, 256>>>(state, enc_W, enc_b, enc_g, enc_bt,
                                       p_s1, ROWS, 250, 250);
    gemm_kernel<0><<<ROWS / 64, 256>>>(p_s1, core_W, nullptr, nullptr, nullptr,
                                       p_P, ROWS, 250, 250);
    gemm_kernel<0><<<ROWS / 64, 256>>>(p_s1, core_W + 250 * 250, nullptr, nullptr, nullptr,
                                       p_Q, ROWS, 250, 250);
    pair_kernel<<<NB, 256, SM_TOT * (int)sizeof(float)>>>(
        p_P, p_Q, core_b, core_g, core_bt,
        ctx_W, ctx_b, ctx_g, ctx_bt,
        att_W1, att_b1, att_g, att_bt,
        att_W2, att_b2, p_eff);
    out_gemm_kernel<<<ROWS / 64, 256>>>(p_s1, p_eff, x, out_W, out_b, out);
}